// round 13
// baseline (speedup 1.0000x reference)
#include <cuda_runtime.h>
#include <cstdint>

// ============================================================================
// SpectralNetLoss:
//   2n·loss = Σ_ij W_ij(sq_i + sq_j) − 2 Σ_ij W_ij (y_i·y_j)
// Term 1: in-loop fp32 FFMA on W fragments (exact).
// Term 2: bf16 mma.sync m16n8k16, U = W × Y folded with Y.
// R13 = R12 + half-chunk staging (16 k-cols), 4 stages, depth-2 prefetch,
//   single barrier/stage (wait->bar->compute->issue), k-slot remap (q,q+4 /
//   q+8,q+12) giving conflict-free scalar LDS.32 A reads at RS=20.
// ============================================================================

#define N_DIM     8192
#define KF        64
#define M_TILE    128
#define KHALF     16
#define KSPLIT    9
#define RS        20                        // 20g+q covers all 32 banks -> CF

#define A_BYTES   (M_TILE * RS * 4)         // 10240
#define SQ_BYTE   A_BYTES                   // 16 floats sq_k (64B, pad to 64)
#define B_OFF     (A_BYTES + 64)            // 10304
#define B_BYTES   2048                      // 8 nt x 32 lanes x 8B
#define STAGE_BYTES  (B_OFF + B_BYTES)      // 12352
#define STAGE_FLOATS (STAGE_BYTES / 4)      // 3088
#define N_STAGES  4
#define SMEM_BYTES   (N_STAGES * STAGE_BYTES)   // 49408 (x4 CTA = 197.6KB)

#define NHC       (N_DIM / KHALF)           // 512 half-chunks

// B packed per half-chunk h: [nt][lane] uint2:
//   .x = bf16x2( Y[h*16+q][n], Y[h*16+q+4][n] )   (logical kpair0)
//   .y = bf16x2( Y[h*16+q+8][n], Y[h*16+q+12][n] ) (logical kpair1)
//   n = nt*8+g, lane = g*4+q.  A pack uses the same k bijection.
__device__ float g_Bp[(size_t)NHC * B_BYTES / 4];
__device__ float g_sq[N_DIM];

// ---------------------------------------------------------------- helpers
__device__ __forceinline__ uint32_t smem_u32(const void* p) {
    uint32_t a;
    asm("{ .reg .u64 t; cvta.to.shared.u64 t, %1; cvt.u32.u64 %0, t; }"
        : "=r"(a) : "l"(p));
    return a;
}
__device__ __forceinline__ void cp_async16(uint32_t dst, const void* src) {
    asm volatile("cp.async.cg.shared.global [%0], [%1], 16;"
                 :: "r"(dst), "l"(src));
}
__device__ __forceinline__ void cp_commit() {
    asm volatile("cp.async.commit_group;" ::: "memory");
}
__device__ __forceinline__ void cp_wait2() {
    asm volatile("cp.async.wait_group 2;" ::: "memory");
}
__device__ __forceinline__ uint32_t bf16pair(float lo, float hi) {
    uint32_t r;   // hi -> upper 16 bits, lo -> lower 16 bits
    asm("cvt.rn.bf16x2.f32 %0, %1, %2;" : "=r"(r) : "f"(hi), "f"(lo));
    return r;
}
__device__ __forceinline__ void mma_bf16(float* c, const uint32_t* a,
                                         uint32_t b0, uint32_t b1) {
    asm volatile(
        "mma.sync.aligned.m16n8k16.row.col.f32.bf16.bf16.f32 "
        "{%0,%1,%2,%3}, {%4,%5,%6,%7}, {%8,%9}, {%0,%1,%2,%3};"
        : "+f"(c[0]), "+f"(c[1]), "+f"(c[2]), "+f"(c[3])
        : "r"(a[0]), "r"(a[1]), "r"(a[2]), "r"(a[3]), "r"(b0), "r"(b1));
}

// ---------------------------------------------------------------- fused prep
// Block b: k-rows [b*32, b*32+32) -> sq + bf16 packs of half-chunks 2b, 2b+1.
__global__ void spec_prep(const float* __restrict__ Y, float* __restrict__ out) {
    __shared__ float sY[32 * 72];           // [k][n], stride 72
    const int tid = threadIdx.x;
    const int b = blockIdx.x;
    const int k0g = b * 32;

    if (b == 0 && tid == 0) out[0] = 0.0f;

#pragma unroll
    for (int i = 0; i < 8; i++) {
        int idx = tid + i * 256;            // coalesced 32x64 load
        sY[(idx >> 6) * 72 + (idx & 63)] = Y[(size_t)k0g * KF + idx];
    }
    __syncthreads();

    {   // sq: 8 threads per row
        int r = tid >> 3, p = tid & 7;
        const float* row = sY + r * 72 + p * 8;
        float s = 0.0f;
#pragma unroll
        for (int c = 0; c < 8; c++) s += row[c] * row[c];
#pragma unroll
        for (int o = 4; o; o >>= 1) s += __shfl_xor_sync(0xffffffffu, s, o);
        if (p == 0) g_sq[k0g + r] = s;
    }

    // pack: 2 half-chunks x 256 uint2; 2 per thread, coalesced 8B writes
#pragma unroll
    for (int i = 0; i < 2; i++) {
        int u = tid + i * 256;
        int hl  = u >> 8;                   // half-chunk within block
        int rem = u & 255;                  // nt*32 + lane
        int lane = rem & 31;
        int nt   = rem >> 5;
        int q = lane & 3, g = lane >> 2;
        int n  = nt * 8 + g;
        int kb = hl * 16;
        uint2 v;
        v.x = bf16pair(sY[(kb + q) * 72 + n],     sY[(kb + q + 4) * 72 + n]);
        v.y = bf16pair(sY[(kb + q + 8) * 72 + n], sY[(kb + q + 12) * 72 + n]);
        *(uint2*)((char*)g_Bp + (size_t)(b * 2 + hl) * B_BYTES + rem * 8) = v;
    }
}

// ---------------------------------------------------------------- loader
__device__ __forceinline__ void load_stage(uint32_t sdst, const float* wp,
                                           const char* bp, const float* sp,
                                           int tid) {
#pragma unroll
    for (int u = 0; u < 4; u++) {
        int idx = tid + u * 128;                      // A: 128 rows x 4 float4
        int r = idx >> 2, sg = idx & 3;
        cp_async16(sdst + (uint32_t)(r * RS + sg * 4) * 4,
                   wp + (size_t)r * N_DIM + sg * 4);
    }
    cp_async16(sdst + B_OFF + tid * 16, bp + tid * 16);   // B pack: 2KB
    if (tid < 4)                                          // sq_k: 64B
        cp_async16(sdst + SQ_BYTE + tid * 16, sp + tid * 4);
}

// ---------------------------------------------------------------- main
__global__ void __launch_bounds__(128, 4)
spec_main(const float* __restrict__ W, const float* __restrict__ Y,
          float* __restrict__ out) {
    extern __shared__ float smem[];
    const uint32_t sb = smem_u32(smem);

    const int tid = threadIdx.x;
    const int w   = tid >> 5;          // warp 0..3: rows [w*32, w*32+32)
    const int lid = tid & 31;
    const int q   = lid & 3;
    const int g   = lid >> 2;
    const int w32 = w * 32;

    const int bx    = blockIdx.x;
    const int mtile = bx & 63;
    const int ks    = bx >> 6;                              // 0..8
    const int m0    = mtile * M_TILE;
    const int c0h   = (ks < 4) ? ks * 58 : 232 + (ks - 4) * 56;
    const int nhc   = (ks < 4) ? 58 : 56;

    const float* wbase = W + (size_t)m0 * N_DIM + (size_t)c0h * KHALF;
    const char*  bbase = (const char*)g_Bp + (size_t)c0h * B_BYTES;
    const float* sbase = g_sq + (size_t)c0h * KHALF;

    // row squared-norms for this thread's 4 fragment rows
    const int rbase = m0 + w32 + g;
    float sqi[2][2];
    sqi[0][0] = g_sq[rbase];      sqi[0][1] = g_sq[rbase + 8];
    sqi[1][0] = g_sq[rbase + 16]; sqi[1][1] = g_sq[rbase + 24];

    float acc[2][8][4];
#pragma unroll
    for (int mt = 0; mt < 2; mt++)
#pragma unroll
        for (int nt = 0; nt < 8; nt++)
#pragma unroll
            for (int v = 0; v < 4; v++) acc[mt][nt][v] = 0.0f;
    float scal = 0.0f;

    // prologue: stages 0..2 in flight
#pragma unroll
    for (int p = 0; p < 3; p++) {
        load_stage(sb + p * STAGE_BYTES, wbase + (size_t)p * KHALF,
                   bbase + (size_t)p * B_BYTES, sbase + p * KHALF, tid);
        cp_commit();
    }

    for (int h = 0; h < nhc; h++) {
        cp_wait2();                        // stage h resident (this warp)
        __syncthreads();                   // ... and all warps' portions

        const float* As = smem + (h & 3) * STAGE_FLOATS;
        const float* Ss = As + SQ_BYTE / 4;
        const char*  Bb = (const char*)smem + (h & 3) * STAGE_BYTES + B_OFF +
                          lid * 8;

        // sq_k at this thread's 4 physical k slots (broadcast LDS)
        float sq0 = Ss[q], sq1 = Ss[q + 4], sq2 = Ss[q + 8], sq3 = Ss[q + 12];

        // A fragments: 16 conflict-free scalar LDS.32 (fp32), term1 FFMA, cvt
        uint32_t a[2][4];
#pragma unroll
        for (int mt = 0; mt < 2; mt++) {
            const float* ap = As + (w32 + mt * 16 + g) * RS;
            const float* hp = ap + 8 * RS;
            float v0 = ap[q], v1 = ap[q + 4], v2 = ap[q + 8], v3 = ap[q + 12];
            float h0 = hp[q], h1 = hp[q + 4], h2 = hp[q + 8], h3 = hp[q + 12];
            scal += v0 * (sqi[mt][0] + sq0) + v1 * (sqi[mt][0] + sq1)
                  + v2 * (sqi[mt][0] + sq2) + v3 * (sqi[mt][0] + sq3)
                  + h0 * (sqi[mt][1] + sq0) + h1 * (sqi[mt][1] + sq1)
                  + h2 * (sqi[mt][1] + sq2) + h3 * (sqi[mt][1] + sq3);
            a[mt][0] = bf16pair(v0, v1);
            a[mt][1] = bf16pair(h0, h1);
            a[mt][2] = bf16pair(v2, v3);
            a[mt][3] = bf16pair(h2, h3);
        }
        // B fragments: one conflict-free LDS.64 per nt
#pragma unroll
        for (int nt = 0; nt < 8; nt++) {
            uint2 bb = *(const uint2*)(Bb + nt * 256);
            mma_bf16(acc[0][nt], a[0], bb.x, bb.y);
            mma_bf16(acc[1][nt], a[1], bb.x, bb.y);
        }

        // issue stage h+3 (stage reuse safe: all warps passed this iter's bar)
        if (h + 3 < nhc)
            load_stage(sb + ((h + 3) & 3) * STAGE_BYTES,
                       wbase + (size_t)(h + 3) * KHALF,
                       bbase + (size_t)(h + 3) * B_BYTES,
                       sbase + (h + 3) * KHALF, tid);
        cp_commit();                       // empty groups keep count aligned
    }

    // ------------- epilogue: fold U with Y, reduce to scalar ---------------
    float dot = 0.0f;
#pragma unroll
    for (int mt = 0; mt < 2; mt++) {
        const int r0 = m0 + w32 + mt * 16 + g;
#pragma unroll
        for (int nt = 0; nt < 8; nt++) {
            const int cc = nt * 8 + 2 * q;
            float2 y0 = *(const float2*)(Y + (size_t)r0 * KF + cc);
            float2 y1 = *(const float2*)(Y + (size_t)(r0 + 8) * KF + cc);
            dot += acc[mt][nt][0] * y0.x + acc[mt][nt][1] * y0.y +
                   acc[mt][nt][2] * y1.x + acc[mt][nt][3] * y1.y;
        }
    }
    float total = scal - 2.0f * dot;
#pragma unroll
    for (int o = 16; o; o >>= 1)
        total += __shfl_xor_sync(0xffffffffu, total, o);

    __syncthreads();                   // all stage reads done before smem reuse
    if (lid == 0) smem[w] = total;
    __syncthreads();
    if (tid == 0) {
        atomicAdd(out, (smem[0] + smem[1] + smem[2] + smem[3]) *
                           (1.0f / (2.0f * (float)N_DIM)));
    }
}

// ---------------------------------------------------------------- launch
extern "C" void kernel_launch(void* const* d_in, const int* in_sizes, int n_in,
                              void* d_out, int out_size) {
    const float* W = (const float*)d_in[0];
    const float* Y = (const float*)d_in[1];
    float* out = (float*)d_out;

    cudaFuncSetAttribute(spec_main, cudaFuncAttributeMaxDynamicSharedMemorySize,
                         SMEM_BYTES);

    spec_prep<<<N_DIM / 32, 256>>>(Y, out);
    spec_main<<<64 * KSPLIT, 128, SMEM_BYTES>>>(W, Y, out);
}

// round 14
// speedup vs baseline: 1.0303x; 1.0303x over previous
#include <cuda_runtime.h>
#include <cstdint>

// ============================================================================
// SpectralNetLoss:
//   2n·loss = Σ_ij W_ij(sq_i + sq_j) − 2 Σ_ij W_ij (y_i·y_j)
// ALL terms via one bf16 mma.sync m16n8k16 GEMM U = W × B̃,
//   B̃ = [Y | sq | 1 | 0…] (72 cols, 9 n8-fragments, rn-bf16 -> unbiased):
//   U[:,0..63] folded with Y -> dot;  U[:,64]=(W·sq)_i, U[:,65]=r_i -> term1.
// R14 = R12 structure exactly (128 thr, 4 warps x (2M x 8N), RS=40, 2-stage
//   32k-chunk cp.async, wait1/bar/compute/bar, KSPLIT=9) + 9th fragment
//   replacing the in-loop fp32 scal path (-26% loop instructions).
// ============================================================================

#define N_DIM     8192
#define KF        64
#define M_TILE    128
#define KCHUNK    32
#define KSPLIT    9
#define RS        40                        // R12-proven conflict-free stride

#define A_FLOATS  (M_TILE * RS)             // 5120
#define B_OFF     (A_FLOATS * 4)            // 20480
#define B_BYTES   4608                      // 2 kst x 9 nt x 32 lanes x 8B
#define STAGE_BYTES  (B_OFF + B_BYTES)      // 25088
#define STAGE_FLOATS (STAGE_BYTES / 4)      // 6272
#define SMEM_BYTES   (2 * STAGE_BYTES)      // 50176 (x4 CTA = 200.7KB)

#define NCHUNK    (N_DIM / KCHUNK)          // 256

// B̃ packed per chunk c: [kst][nt][lane] uint2, lane = g*4+q:
//   .x = bf16x2( B̃[k0][n], B̃[k0+1][n] ),  .y = bf16x2( B̃[k0+8][n], B̃[k0+9][n] )
//   k0 = c*32 + kst*16 + 2q, n = nt*8+g.  nt=8 -> cols 64..71 = [sq|1|0…].
__device__ float g_Bp[(size_t)NCHUNK * B_BYTES / 4];
__device__ float g_sq[N_DIM];

// ---------------------------------------------------------------- helpers
__device__ __forceinline__ uint32_t smem_u32(const void* p) {
    uint32_t a;
    asm("{ .reg .u64 t; cvta.to.shared.u64 t, %1; cvt.u32.u64 %0, t; }"
        : "=r"(a) : "l"(p));
    return a;
}
__device__ __forceinline__ void cp_async16(uint32_t dst, const void* src) {
    asm volatile("cp.async.cg.shared.global [%0], [%1], 16;"
                 :: "r"(dst), "l"(src));
}
__device__ __forceinline__ void cp_commit() {
    asm volatile("cp.async.commit_group;" ::: "memory");
}
__device__ __forceinline__ void cp_wait1() {
    asm volatile("cp.async.wait_group 1;" ::: "memory");
}
__device__ __forceinline__ void cp_wait0() {
    asm volatile("cp.async.wait_group 0;" ::: "memory");
}
__device__ __forceinline__ uint32_t bf16pair(float lo, float hi) {
    uint32_t r;   // hi -> upper 16 bits, lo -> lower 16 bits
    asm("cvt.rn.bf16x2.f32 %0, %1, %2;" : "=r"(r) : "f"(hi), "f"(lo));
    return r;
}
__device__ __forceinline__ void mma_bf16(float* c, const uint32_t* a,
                                         uint32_t b0, uint32_t b1) {
    asm volatile(
        "mma.sync.aligned.m16n8k16.row.col.f32.bf16.bf16.f32 "
        "{%0,%1,%2,%3}, {%4,%5,%6,%7}, {%8,%9}, {%0,%1,%2,%3};"
        : "+f"(c[0]), "+f"(c[1]), "+f"(c[2]), "+f"(c[3])
        : "r"(a[0]), "r"(a[1]), "r"(a[2]), "r"(a[3]), "r"(b0), "r"(b1));
}

// ---------------------------------------------------------------- fused prep
// Block b handles k-rows [b*32, b*32+32) = chunk b: sq + bf16 B̃ pack.
__global__ void spec_prep(const float* __restrict__ Y, float* __restrict__ out) {
    __shared__ float sY[32 * 72];           // [k][n], stride 72
    __shared__ float ssq[32];
    const int tid = threadIdx.x;
    const int b = blockIdx.x;
    const int k0g = b * 32;

    if (b == 0 && tid == 0) out[0] = 0.0f;

#pragma unroll
    for (int i = 0; i < 8; i++) {
        int idx = tid + i * 256;            // coalesced 32x64 load
        sY[(idx >> 6) * 72 + (idx & 63)] = Y[(size_t)k0g * KF + idx];
    }
    __syncthreads();

    {   // sq: 8 threads per row
        int r = tid >> 3, p = tid & 7;
        const float* row = sY + r * 72 + p * 8;
        float s = 0.0f;
#pragma unroll
        for (int c = 0; c < 8; c++) s += row[c] * row[c];
#pragma unroll
        for (int o = 4; o; o >>= 1) s += __shfl_xor_sync(0xffffffffu, s, o);
        if (p == 0) { ssq[r] = s; g_sq[k0g + r] = s; }
    }
    __syncthreads();

    // pack: 2 kst x 9 nt x 32 lanes = 576 uint2; coalesced 8B writes
#pragma unroll
    for (int i = 0; i < 3; i++) {
        int u = tid + i * 256;              // [kst][nt][lane]
        if (u >= 576) break;
        int lane = u & 31;
        int nt   = (u >> 5) % 9;
        int kst  = u / 288;
        int q = lane & 3, g = lane >> 2;
        int ka = kst * 16 + 2 * q;          // k rel. to chunk
        uint2 v;
        if (nt < 8) {
            int n = nt * 8 + g;
            v.x = bf16pair(sY[ka * 72 + n],       sY[(ka + 1) * 72 + n]);
            v.y = bf16pair(sY[(ka + 8) * 72 + n], sY[(ka + 9) * 72 + n]);
        } else if (g == 0) {                // col 64 = sq_k
            v.x = bf16pair(ssq[ka],     ssq[ka + 1]);
            v.y = bf16pair(ssq[ka + 8], ssq[ka + 9]);
        } else if (g == 1) {                // col 65 = ones
            v.x = bf16pair(1.0f, 1.0f);
            v.y = v.x;
        } else {                            // cols 66..71 = zeros
            v.x = 0u; v.y = 0u;
        }
        *(uint2*)((char*)g_Bp + (size_t)b * B_BYTES + u * 8) = v;
    }
}

// ---------------------------------------------------------------- loader
__device__ __forceinline__ void load_chunk(uint32_t sdst, const float* wp,
                                           const char* bp, int tid) {
#pragma unroll
    for (int u = 0; u < 8; u++) {
        int idx = tid + u * 128;                      // A: 128 rows x 8 float4
        int r = idx >> 3, sg = idx & 7;
        cp_async16(sdst + (uint32_t)(r * RS + sg * 4) * 4,
                   wp + (size_t)r * N_DIM + sg * 4);
    }
#pragma unroll
    for (int u = 0; u < 3; u++) {                     // B̃ pack: 4608B
        int idx = tid + u * 128;
        if (idx < B_BYTES / 16)
            cp_async16(sdst + B_OFF + idx * 16, bp + idx * 16);
    }
}

// ---------------------------------------------------------------- main
__global__ void __launch_bounds__(128, 4)
spec_main(const float* __restrict__ W, const float* __restrict__ Y,
          float* __restrict__ out) {
    extern __shared__ float smem[];
    const uint32_t sb = smem_u32(smem);

    const int tid = threadIdx.x;
    const int w   = tid >> 5;          // warp 0..3: rows [w*32, w*32+32)
    const int lid = tid & 31;
    const int q   = lid & 3;
    const int g   = lid >> 2;
    const int w32 = w * 32;

    const int bx    = blockIdx.x;
    const int mtile = bx & 63;
    const int ks    = bx >> 6;                              // 0..8
    const int m0    = mtile * M_TILE;
    const int c0    = (ks < 4) ? ks * 29 : 116 + (ks - 4) * 28;
    const int nch   = (ks < 4) ? 29 : 28;

    const float* wbase = W + (size_t)m0 * N_DIM + (size_t)c0 * KCHUNK;
    const char*  bbase = (const char*)g_Bp + (size_t)c0 * B_BYTES;

    float acc[2][8][4];
    float acc_e[2][4];
#pragma unroll
    for (int mt = 0; mt < 2; mt++) {
#pragma unroll
        for (int nt = 0; nt < 8; nt++)
#pragma unroll
            for (int v = 0; v < 4; v++) acc[mt][nt][v] = 0.0f;
#pragma unroll
        for (int v = 0; v < 4; v++) acc_e[mt][v] = 0.0f;
    }

    // prologue: chunk 0 in flight
    load_chunk(sb, wbase, bbase, tid);
    cp_commit();

    for (int j = 0; j < nch; j++) {
        if (j + 1 < nch) {
            load_chunk(sb + ((j + 1) & 1) * STAGE_BYTES,
                       wbase + (size_t)(j + 1) * KCHUNK,
                       bbase + (size_t)(j + 1) * B_BYTES, tid);
            cp_commit();
            cp_wait1();
        } else {
            cp_wait0();
        }
        __syncthreads();

        const float* As = smem + (j & 1) * STAGE_FLOATS;
        const char*  Bb = (const char*)smem + (j & 1) * STAGE_BYTES + B_OFF +
                          lid * 8;

#pragma unroll
        for (int kst = 0; kst < 2; kst++) {
            const int k0 = kst * 16 + 2 * q;
            // A fragments: 4x conflict-free LDS.64 per mt (fp32 -> bf16x2)
            uint32_t a[2][4];
#pragma unroll
            for (int mt = 0; mt < 2; mt++) {
                const float* ap = As + (w32 + mt * 16 + g) * RS + k0;
                float2 p00 = *(const float2*)ap;             // row g,   k +0,+1
                float2 p01 = *(const float2*)(ap + 8);       // row g,   k +8,+9
                float2 p10 = *(const float2*)(ap + 8 * RS);  // row g+8
                float2 p11 = *(const float2*)(ap + 8 * RS + 8);
                a[mt][0] = bf16pair(p00.x, p00.y);
                a[mt][1] = bf16pair(p10.x, p10.y);
                a[mt][2] = bf16pair(p01.x, p01.y);
                a[mt][3] = bf16pair(p11.x, p11.y);
            }
            // B̃ fragments: one conflict-free LDS.64 per nt (9 total)
            const char* Bk = Bb + kst * (B_BYTES / 2);
#pragma unroll
            for (int nt = 0; nt < 8; nt++) {
                uint2 bb = *(const uint2*)(Bk + nt * 256);
                mma_bf16(acc[0][nt], a[0], bb.x, bb.y);
                mma_bf16(acc[1][nt], a[1], bb.x, bb.y);
            }
            {
                uint2 bb = *(const uint2*)(Bk + 8 * 256);
                mma_bf16(acc_e[0], a[0], bb.x, bb.y);
                mma_bf16(acc_e[1], a[1], bb.x, bb.y);
            }
        }
        __syncthreads();
    }

    // ------------- epilogue: fold U with Y + extra cols, reduce -------------
    const int rbase = m0 + w32 + g;
    float sqi[2][2];
    sqi[0][0] = g_sq[rbase];      sqi[0][1] = g_sq[rbase + 8];
    sqi[1][0] = g_sq[rbase + 16]; sqi[1][1] = g_sq[rbase + 24];

    float dot = 0.0f, extra = 0.0f;
#pragma unroll
    for (int mt = 0; mt < 2; mt++) {
        const int r0 = m0 + w32 + mt * 16 + g;
#pragma unroll
        for (int nt = 0; nt < 8; nt++) {
            const int cc = nt * 8 + 2 * q;
            float2 y0 = *(const float2*)(Y + (size_t)r0 * KF + cc);
            float2 y1 = *(const float2*)(Y + (size_t)(r0 + 8) * KF + cc);
            dot += acc[mt][nt][0] * y0.x + acc[mt][nt][1] * y0.y +
                   acc[mt][nt][2] * y1.x + acc[mt][nt][3] * y1.y;
        }
        // q==0 lanes: c0 = col64 = (W·sq)_i, c1 = col65 = rowsum r_i
        // (rows g / g+8); q>=1 lanes hold zero columns -> exact 0.
        extra += acc_e[mt][0] + sqi[mt][0] * acc_e[mt][1] +
                 acc_e[mt][2] + sqi[mt][1] * acc_e[mt][3];
    }
    float total = extra - 2.0f * dot;
#pragma unroll
    for (int o = 16; o; o >>= 1)
        total += __shfl_xor_sync(0xffffffffu, total, o);

    if (lid == 0) smem[w] = total;     // stages dead after final chunk barrier
    __syncthreads();
    if (tid == 0) {
        atomicAdd(out, (smem[0] + smem[1] + smem[2] + smem[3]) *
                           (1.0f / (2.0f * (float)N_DIM)));
    }
}

// ---------------------------------------------------------------- launch
extern "C" void kernel_launch(void* const* d_in, const int* in_sizes, int n_in,
                              void* d_out, int out_size) {
    const float* W = (const float*)d_in[0];
    const float* Y = (const float*)d_in[1];
    float* out = (float*)d_out;

    cudaFuncSetAttribute(spec_main, cudaFuncAttributeMaxDynamicSharedMemorySize,
                         SMEM_BYTES);

    spec_prep<<<NCHUNK, 256>>>(Y, out);
    spec_main<<<64 * KSPLIT, 128, SMEM_BYTES>>>(W, Y, out);
}